// round 14
// baseline (speedup 1.0000x reference)
#include <cuda_runtime.h>
#include <cuda_fp16.h>
#include <cstdint>

#define UNITS 128
#define QDIM 256
#define VDIM 256
#define BATCH 128
#define SEQ 4096
#define TM 64
#define NT2 8192
#define GRID_A 304

__device__ float g_qproj[BATCH*UNITS];
__device__ __half g_bhi[UNITS*VDIM];
__device__ float g_escore[BATCH*SEQ];
__device__ float g_psum[NT2];
__device__ float g_pctx[NT2*VDIM];
__device__ unsigned g_arrive;

/* smem map (bytes) per CTA */
#define SM_BH 0               /* 64 KB */
#define SM_A0 65536           /* 4 chunk buffers x 8192 */
#define SM_QROW 98304
#define SM_WV 98816
#define SM_SRED 99328
#define SM_WRED 99840
#define SM_SW 99904
#define SM_CTX 100160         /* 8 x 256 floats */
#define SM_TOTAL 108352

#define LDSM4(f, addr) asm volatile( \
  "ldmatrix.sync.aligned.m8n8.x4.shared.b16 {%0,%1,%2,%3}, [%4];" \
  : "=r"((f)[0]),"=r"((f)[1]),"=r"((f)[2]),"=r"((f)[3]) : "r"(addr))

#define MMAH(dd, aa, b0, b1) asm volatile( \
  "mma.sync.aligned.m16n8k16.row.col.f16.f16.f16.f16 {%0,%1}, {%2,%3,%4,%5}, {%6,%7}, {%0,%1};" \
  : "+r"((dd)[0]),"+r"((dd)[1]) \
  : "r"((aa)[0]),"r"((aa)[1]),"r"((aa)[2]),"r"((aa)[3]),"r"(b0),"r"(b1))

__device__ __forceinline__ uint32_t h2u(__half2 h){ return *(uint32_t*)&h; }

__device__ __forceinline__ float ftanh(float x){
    float y; asm("tanh.approx.f32 %0, %1;" : "=f"(y) : "f"(x)); return y;
}

__global__ void k_prep(const float* __restrict__ q, const float* __restrict__ W1,
                       const float* __restrict__ b1, const float* __restrict__ W2,
                       const float* __restrict__ b2){
    if (blockIdx.x < BATCH){
        int b = blockIdx.x, u = threadIdx.x;
        float acc = b1[u] + b2[u];
        #pragma unroll 8
        for (int k = 0; k < QDIM; k++) acc = fmaf(q[b*QDIM+k], W1[k*UNITS+u], acc);
        g_qproj[b*UNITS+u] = acc;
    } else {
        for (int i = threadIdx.x; i < UNITS*VDIM; i += 128){
            int u = i >> 8, k = i & 255;
            g_bhi[u*VDIM+k] = __float2half_rn(W2[k*UNITS+u]);
        }
    }
}

__global__ void __launch_bounds__(256,2)
k_scores(const float* __restrict__ values, const float* __restrict__ Wv,
         const float* __restrict__ bv, float* __restrict__ outw, float* __restrict__ outc){
    extern __shared__ char smem[];
    const int tid = threadIdx.x;
    const int lane = tid & 31;
    const int wid = tid >> 5;
    const int warp_m = wid & 3;
    const int warp_n = wid >> 2;

    uint32_t sbase;
    asm("{ .reg .u64 t; cvta.to.shared.u64 t, %1; cvt.u32.u64 %0, t; }":"=r"(sbase):"l"(smem));

    #pragma unroll
    for (int j = 0; j < 16; j++){
        int G = j*256 + tid;
        int u = G >> 5, g = G & 31;
        int off = u*512 + ((g ^ (u&7))<<4);
        *(uint4*)(smem + SM_BH + off) = ((const uint4*)g_bhi)[G];
    }
    if (tid < UNITS) ((float*)(smem+SM_WV))[tid] = Wv[tid];
    const float bvv = bv[0];
    float* qrow = (float*)(smem+SM_QROW);
    float* wvs  = (float*)(smem+SM_WV);
    float* sred = (float*)(smem+SM_SRED);
    float* wred = (float*)(smem+SM_WRED);
    float* sw   = (float*)(smem+SM_SW);
    float* sctx = (float*)(smem+SM_CTX);

    const int a_r = warp_m*16 + ((lane>>3)&1)*8 + (lane&7);
    const uint32_t a_base0 = sbase + SM_A0 + a_r*128;
    const int a_r7 = a_r & 7;
    const int gA_l = (lane>>4);
    uint32_t b_base[4]; int b_n7[4];
    #pragma unroll
    for (int nf2 = 0; nf2 < 4; nf2++){
        int n = warp_n*64 + nf2*16 + (lane>>4)*8 + (lane&7);
        b_base[nf2] = sbase + SM_BH + n*512;
        b_n7[nf2] = n & 7;
    }
    const int gB_l = ((lane>>3)&1);
    const int srow = tid >> 2;
    const int sq = tid & 3;
    const int soff = srow*128 + (((sq*2) ^ (srow&7))<<4);
    const int soff2 = srow*128 + (((sq*2+1) ^ (srow&7))<<4);

    /* context mapping: 8 dims x 8 rows per thread */
    const int cg8 = tid & 31;
    const int rq = tid >> 5;
    const uint32_t ctx_base = sbase + SM_A0 + (cg8>>3)*8192;
    const int ctx_gr = cg8 & 7;

    int tile = blockIdx.x;
    float4 pv[8];
    {
        const int b = tile >> 6, s0 = (tile & 63) * TM;
        const float* vp0 = values + ((size_t)(b*SEQ + s0 + srow))*VDIM + sq*16;
        #pragma unroll
        for (int j = 0; j < 4; j++) pv[j] = ((const float4*)vp0)[j];
        #pragma unroll
        for (int j = 0; j < 4; j++) pv[4+j] = ((const float4*)(vp0+64))[j];
    }

    for (; tile < NT2; tile += GRID_A){
        const int b = tile >> 6, s0 = (tile & 63) * TM;
        const float* vp = values + ((size_t)(b*SEQ + s0 + srow))*VDIM + sq*16;
        if (tid < 128) qrow[tid] = g_qproj[b*UNITS + tid];
        uint32_t d[8][2] = {};

        auto cvt_chunk = [&](const float4* p, int buf){
            char* bufp = smem + SM_A0 + buf*8192;
            __half2 h0=__floats2half2_rn(p[0].x,p[0].y), h1=__floats2half2_rn(p[0].z,p[0].w);
            __half2 h2=__floats2half2_rn(p[1].x,p[1].y), h3=__floats2half2_rn(p[1].z,p[1].w);
            __half2 h4=__floats2half2_rn(p[2].x,p[2].y), h5=__floats2half2_rn(p[2].z,p[2].w);
            __half2 h6=__floats2half2_rn(p[3].x,p[3].y), h7=__floats2half2_rn(p[3].z,p[3].w);
            *(uint4*)(bufp + soff)  = make_uint4(h2u(h0),h2u(h1),h2u(h2),h2u(h3));
            *(uint4*)(bufp + soff2) = make_uint4(h2u(h4),h2u(h5),h2u(h6),h2u(h7));
        };
        auto mma_chunk = [&](int kc){
            const uint32_t abase = a_base0 + (uint32_t)(kc*8192);
            #pragma unroll
            for (int ks = 0; ks < 4; ks++){
                uint32_t a[4];
                int gA = ks*2 + gA_l;
                LDSM4(a, abase + ((gA ^ a_r7)<<4));
                #pragma unroll
                for (int nf2 = 0; nf2 < 4; nf2++){
                    int gB = kc*8 + ks*2 + gB_l;
                    uint32_t bh[4];
                    LDSM4(bh, b_base[nf2] + ((gB ^ b_n7[nf2])<<4));
                    MMAH(d[2*nf2],   a, bh[0], bh[1]);
                    MMAH(d[2*nf2+1], a, bh[2], bh[3]);
                }
            }
        };

        /* stage c0,c1 from prefetch regs; issue LDG c2,c3 */
        cvt_chunk(pv, 0);
        cvt_chunk(pv+4, 1);
        float4 v[8];
        #pragma unroll
        for (int j = 0; j < 4; j++) v[j] = ((const float4*)(vp+128))[j];
        #pragma unroll
        for (int j = 0; j < 4; j++) v[4+j] = ((const float4*)(vp+192))[j];
        __syncthreads();                       /* s1 */

        mma_chunk(0);
        cvt_chunk(v, 2);
        mma_chunk(1);
        cvt_chunk(v+4, 3);
        __syncthreads();                       /* s2 */

        mma_chunk(2);
        mma_chunk(3);
        /* prefetch next tile c0,c1 */
        {
            int nt = tile + GRID_A;
            if (nt < NT2){
                const int b2 = nt >> 6, s02 = (nt & 63) * TM;
                const float* vpn = values + ((size_t)(b2*SEQ + s02 + srow))*VDIM + sq*16;
                #pragma unroll
                for (int j = 0; j < 4; j++) pv[j] = ((const float4*)vpn)[j];
                #pragma unroll
                for (int j = 0; j < 4; j++) pv[4+j] = ((const float4*)(vpn+64))[j];
            }
        }

        /* score part */
        float part[2] = {0.f, 0.f};
        #pragma unroll
        for (int nf = 0; nf < 8; nf++){
            int col = warp_n*64 + nf*8 + (lane&3)*2;
            #pragma unroll
            for (int p = 0; p < 2; p++){
                float2 f = __half22float2(*(__half2*)&d[nf][p]);
                part[p] = fmaf(wvs[col],   ftanh(f.x + qrow[col]),   part[p]);
                part[p] = fmaf(wvs[col+1], ftanh(f.y + qrow[col+1]), part[p]);
            }
        }
        #pragma unroll
        for (int p = 0; p < 2; p++){
            part[p] += __shfl_xor_sync(0xffffffffu, part[p], 1);
            part[p] += __shfl_xor_sync(0xffffffffu, part[p], 2);
        }
        if ((lane & 3) == 0){
            #pragma unroll
            for (int p = 0; p < 2; p++){
                int row = warp_m*16 + (lane>>2) + p*8;
                sred[warp_n*64 + row] = part[p];
            }
        }
        __syncthreads();                       /* s3 */
        if (tid < TM){
            float e = __expf(sred[tid] + sred[64+tid] + bvv);
            g_escore[b*SEQ + s0 + tid] = e;
            sw[tid] = e;
            #pragma unroll
            for (int o = 16; o; o >>= 1) e += __shfl_xor_sync(0xffffffffu, e, o);
            if (lane == 0) wred[tid>>5] = e;
        }
        __syncthreads();                       /* s4 */

        /* fused context */
        {
            float acc[8] = {};
            #pragma unroll
            for (int r0 = 0; r0 < 8; r0++){
                int r = rq*8 + r0;
                uint32_t addr = ctx_base + (uint32_t)(r*128 + ((ctx_gr ^ (r&7))<<4));
                uint4 u;
                asm volatile("ld.shared.v4.b32 {%0,%1,%2,%3}, [%4];"
                    : "=r"(u.x),"=r"(u.y),"=r"(u.z),"=r"(u.w) : "r"(addr));
                float w = sw[r];
                float2 f0 = __half22float2(*(__half2*)&u.x);
                float2 f1 = __half22float2(*(__half2*)&u.y);
                float2 f2 = __half22float2(*(__half2*)&u.z);
                float2 f3 = __half22float2(*(__half2*)&u.w);
                acc[0] = fmaf(w, f0.x, acc[0]); acc[1] = fmaf(w, f0.y, acc[1]);
                acc[2] = fmaf(w, f1.x, acc[2]); acc[3] = fmaf(w, f1.y, acc[3]);
                acc[4] = fmaf(w, f2.x, acc[4]); acc[5] = fmaf(w, f2.y, acc[5]);
                acc[6] = fmaf(w, f3.x, acc[6]); acc[7] = fmaf(w, f3.y, acc[7]);
            }
            float* dst = sctx + rq*256 + cg8*8;
            *(float4*)dst = make_float4(acc[0],acc[1],acc[2],acc[3]);
            *(float4*)(dst+4) = make_float4(acc[4],acc[5],acc[6],acc[7]);
        }
        __syncthreads();                       /* s5 */
        if (tid < 128){
            float2* sc = (float2*)sctx;
            float2 a = sc[tid];
            #pragma unroll
            for (int q = 1; q < 8; q++){
                float2 t = sc[q*128 + tid];
                a.x += t.x; a.y += t.y;
            }
            ((float2*)g_pctx)[tile*128 + tid] = a;
        }
        if (tid == 0) g_psum[tile] = wred[0]+wred[1];
    }

    /* ---- grid barrier (monotonic; replay-safe) ---- */
    __syncthreads();
    if (tid == 0){
        __threadfence();
        unsigned my = atomicAdd(&g_arrive, 1u) + 1u;
        unsigned target = ((my + (GRID_A-1)) / GRID_A) * GRID_A;
        while (*((volatile unsigned*)&g_arrive) < target) __nanosleep(64);
        __threadfence();
    }
    __syncthreads();

    /* each CTA computes all 128 inverse sums (L2-hot) */
    if (tid < BATCH){
        float s = 0.f;
        #pragma unroll 8
        for (int t = 0; t < 64; t++) s += g_psum[tid*64 + t];
        qrow[tid] = 1.f / s;
    }
    __syncthreads();

    /* weights output */
    for (int i = blockIdx.x*256 + tid; i < BATCH*SEQ; i += GRID_A*256)
        outw[i] = g_escore[i] * qrow[i >> 12];

    /* context output */
    for (int i = blockIdx.x*256 + tid; i < BATCH*VDIM; i += GRID_A*256){
        int bb = i >> 8, dd2 = i & 255;
        float a = 0.f;
        #pragma unroll 8
        for (int t = 0; t < 64; t++) a += g_pctx[(bb*64 + t)*VDIM + dd2];
        outc[i] = a * qrow[bb];
    }
}

extern "C" void kernel_launch(void* const* d_in, const int* in_sizes, int n_in,
                              void* d_out, int out_size){
    (void)in_sizes; (void)n_in; (void)out_size;
    const float* query  = (const float*)d_in[0];
    const float* values = (const float*)d_in[1];
    const float* W1 = (const float*)d_in[2];
    const float* b1 = (const float*)d_in[3];
    const float* W2 = (const float*)d_in[4];
    const float* b2 = (const float*)d_in[5];
    const float* Wv = (const float*)d_in[6];
    const float* bv = (const float*)d_in[7];
    float* out = (float*)d_out;
    cudaFuncSetAttribute(k_scores, cudaFuncAttributeMaxDynamicSharedMemorySize, SM_TOTAL);
    k_prep<<<BATCH + 1, 128>>>(query, W1, b1, W2, b2);
    k_scores<<<GRID_A, 256, SM_TOTAL>>>(values, Wv, bv, out + BATCH*VDIM, out);
}

// round 16
// speedup vs baseline: 1.1616x; 1.1616x over previous
#include <cuda_runtime.h>
#include <cuda_fp16.h>
#include <cstdint>

#define UNITS 128
#define QDIM 256
#define VDIM 256
#define BATCH 128
#define SEQ 4096
#define TM 64
#define NT2 8192
#define GRID_A 304

__device__ float g_qproj[BATCH*UNITS];
__device__ __half g_bhi[UNITS*VDIM];
__device__ float g_escore[BATCH*SEQ];
__device__ float g_psum[NT2];
__device__ float g_pctx[NT2*VDIM];
__device__ unsigned g_arrive;

/* smem map (bytes) per CTA */
#define SM_BH 0               /* 64 KB */
#define SM_A0 65536           /* 4 chunk buffers x 8192 */
#define SM_QROW 98304
#define SM_WV 98816
#define SM_SRED 99328         /* 4 x 64 floats = 1024 */
#define SM_WRED 100352
#define SM_SW 100416
#define SM_CTX 100672         /* 8 x 256 floats */
#define SM_TOTAL 108864

#define LDSM4(f, addr) asm volatile( \
  "ldmatrix.sync.aligned.m8n8.x4.shared.b16 {%0,%1,%2,%3}, [%4];" \
  : "=r"((f)[0]),"=r"((f)[1]),"=r"((f)[2]),"=r"((f)[3]) : "r"(addr))

#define MMAH(dd, aa, b0, b1) asm volatile( \
  "mma.sync.aligned.m16n8k16.row.col.f16.f16.f16.f16 {%0,%1}, {%2,%3,%4,%5}, {%6,%7}, {%0,%1};" \
  : "+r"((dd)[0]),"+r"((dd)[1]) \
  : "r"((aa)[0]),"r"((aa)[1]),"r"((aa)[2]),"r"((aa)[3]),"r"(b0),"r"(b1))

__device__ __forceinline__ uint32_t h2u(__half2 h){ return *(uint32_t*)&h; }

__device__ __forceinline__ float ftanh(float x){
    float y; asm("tanh.approx.f32 %0, %1;" : "=f"(y) : "f"(x)); return y;
}

__global__ void k_prep(const float* __restrict__ q, const float* __restrict__ W1,
                       const float* __restrict__ b1, const float* __restrict__ W2,
                       const float* __restrict__ b2){
    if (blockIdx.x < BATCH){
        int b = blockIdx.x, u = threadIdx.x;
        float acc = b1[u] + b2[u];
        #pragma unroll 8
        for (int k = 0; k < QDIM; k++) acc = fmaf(q[b*QDIM+k], W1[k*UNITS+u], acc);
        g_qproj[b*UNITS+u] = acc;
    } else {
        for (int i = threadIdx.x; i < UNITS*VDIM; i += 128){
            int u = i >> 8, k = i & 255;
            g_bhi[u*VDIM+k] = __float2half_rn(W2[k*UNITS+u]);
        }
    }
}

__global__ void __launch_bounds__(256,2)
k_scores(const float* __restrict__ values, const float* __restrict__ Wv,
         const float* __restrict__ bv, float* __restrict__ outw, float* __restrict__ outc){
    extern __shared__ char smem[];
    const int tid = threadIdx.x;
    const int lane = tid & 31;
    const int wid = tid >> 5;
    const int warp_m = wid & 1;   /* 2 groups x 32 rows */
    const int warp_n = wid >> 1;  /* 4 groups x 32 units */

    uint32_t sbase;
    asm("{ .reg .u64 t; cvta.to.shared.u64 t, %1; cvt.u32.u64 %0, t; }":"=r"(sbase):"l"(smem));

    #pragma unroll
    for (int j = 0; j < 16; j++){
        int G = j*256 + tid;
        int u = G >> 5, g = G & 31;
        int off = u*512 + ((g ^ (u&7))<<4);
        *(uint4*)(smem + SM_BH + off) = ((const uint4*)g_bhi)[G];
    }
    if (tid < UNITS) ((float*)(smem+SM_WV))[tid] = Wv[tid];
    const float bvv = bv[0];
    float* qrow = (float*)(smem+SM_QROW);
    float* wvs  = (float*)(smem+SM_WV);
    float* sred = (float*)(smem+SM_SRED);
    float* wred = (float*)(smem+SM_WRED);
    float* sw   = (float*)(smem+SM_SW);
    float* sctx = (float*)(smem+SM_CTX);

    /* A: 2 fragment rows (mf=0,1 -> +16 rows); same &7 */
    const int a_r0 = warp_m*32 + ((lane>>3)&1)*8 + (lane&7);
    const uint32_t a_base0 = sbase + SM_A0 + a_r0*128;
    const uint32_t a_base1 = a_base0 + 16*128;
    const int a_r7 = a_r0 & 7;
    const int gA_l = (lane>>4);
    /* B: 2 fragment cols */
    uint32_t b_base[2]; int b_n7[2];
    #pragma unroll
    for (int nf2 = 0; nf2 < 2; nf2++){
        int n = warp_n*32 + nf2*16 + (lane>>4)*8 + (lane&7);
        b_base[nf2] = sbase + SM_BH + n*512;
        b_n7[nf2] = n & 7;
    }
    const int gB_l = ((lane>>3)&1);
    const int srow = tid >> 2;
    const int sq = tid & 3;
    const int soff = srow*128 + (((sq*2) ^ (srow&7))<<4);
    const int soff2 = srow*128 + (((sq*2+1) ^ (srow&7))<<4);

    /* context mapping: 8 dims x 8 rows per thread */
    const int cg8 = tid & 31;
    const int rq = tid >> 5;
    const uint32_t ctx_base = sbase + SM_A0 + (cg8>>3)*8192;
    const int ctx_gr = cg8 & 7;

    int tile = blockIdx.x;
    float4 pv[4];
    {
        const int b = tile >> 6, s0 = (tile & 63) * TM;
        const float* vp0 = values + ((size_t)(b*SEQ + s0 + srow))*VDIM + sq*16;
        #pragma unroll
        for (int j = 0; j < 4; j++) pv[j] = ((const float4*)vp0)[j];
    }

    for (; tile < NT2; tile += GRID_A){
        const int b = tile >> 6, s0 = (tile & 63) * TM;
        const float* vp = values + ((size_t)(b*SEQ + s0 + srow))*VDIM + sq*16;
        if (tid < 128) qrow[tid] = g_qproj[b*UNITS + tid];
        uint32_t d[2][4][2] = {};
        {   /* convert prefetched chunk 0 */
            float4 p0 = pv[0], p1 = pv[1], p2 = pv[2], p3 = pv[3];
            __half2 h0=__floats2half2_rn(p0.x,p0.y), h1=__floats2half2_rn(p0.z,p0.w);
            __half2 h2=__floats2half2_rn(p1.x,p1.y), h3=__floats2half2_rn(p1.z,p1.w);
            __half2 h4=__floats2half2_rn(p2.x,p2.y), h5=__floats2half2_rn(p2.z,p2.w);
            __half2 h6=__floats2half2_rn(p3.x,p3.y), h7=__floats2half2_rn(p3.z,p3.w);
            *(uint4*)(smem + SM_A0 + soff)  = make_uint4(h2u(h0),h2u(h1),h2u(h2),h2u(h3));
            *(uint4*)(smem + SM_A0 + soff2) = make_uint4(h2u(h4),h2u(h5),h2u(h6),h2u(h7));
        }

        #pragma unroll
        for (int kc = 0; kc < 4; kc++){
            __syncthreads();
            float4 v[4];
            if (kc < 3){
                const float* vp2 = vp + (kc+1)*64;
                #pragma unroll
                for (int j = 0; j < 4; j++) v[j] = ((const float4*)vp2)[j];
            }
            const uint32_t ab0 = a_base0 + (uint32_t)(kc*8192);
            const uint32_t ab1 = a_base1 + (uint32_t)(kc*8192);
            #pragma unroll
            for (int ks = 0; ks < 4; ks++){
                uint32_t a0[4], a1[4];
                int gA = ks*2 + gA_l;
                LDSM4(a0, ab0 + ((gA ^ a_r7)<<4));
                LDSM4(a1, ab1 + ((gA ^ a_r7)<<4));
                #pragma unroll
                for (int nf2 = 0; nf2 < 2; nf2++){
                    int gB = kc*8 + ks*2 + gB_l;
                    uint32_t bh[4];
                    LDSM4(bh, b_base[nf2] + ((gB ^ b_n7[nf2])<<4));
                    MMAH(d[0][2*nf2],   a0, bh[0], bh[1]);
                    MMAH(d[0][2*nf2+1], a0, bh[2], bh[3]);
                    MMAH(d[1][2*nf2],   a1, bh[0], bh[1]);
                    MMAH(d[1][2*nf2+1], a1, bh[2], bh[3]);
                }
            }
            if (kc < 3){
                char* buf = smem + SM_A0 + (kc+1)*8192;
                float4 p0 = v[0], p1 = v[1], p2 = v[2], p3 = v[3];
                __half2 h0=__floats2half2_rn(p0.x,p0.y), h1=__floats2half2_rn(p0.z,p0.w);
                __half2 h2=__floats2half2_rn(p1.x,p1.y), h3=__floats2half2_rn(p1.z,p1.w);
                __half2 h4=__floats2half2_rn(p2.x,p2.y), h5=__floats2half2_rn(p2.z,p2.w);
                __half2 h6=__floats2half2_rn(p3.x,p3.y), h7=__floats2half2_rn(p3.z,p3.w);
                *(uint4*)(buf + soff)  = make_uint4(h2u(h0),h2u(h1),h2u(h2),h2u(h3));
                *(uint4*)(buf + soff2) = make_uint4(h2u(h4),h2u(h5),h2u(h6),h2u(h7));
            }
        }

        /* prefetch next tile chunk 0 */
        {
            int nt = tile + GRID_A;
            if (nt < NT2){
                const int b2 = nt >> 6, s02 = (nt & 63) * TM;
                const float* vpn = values + ((size_t)(b2*SEQ + s02 + srow))*VDIM + sq*16;
                #pragma unroll
                for (int j = 0; j < 4; j++) pv[j] = ((const float4*)vpn)[j];
            }
        }

        /* epilogue: score part */
        float part[2][2] = {};
        #pragma unroll
        for (int mf = 0; mf < 2; mf++)
            #pragma unroll
            for (int nf = 0; nf < 4; nf++){
                int col = warp_n*32 + nf*8 + (lane&3)*2;
                #pragma unroll
                for (int p = 0; p < 2; p++){
                    float2 f = __half22float2(*(__half2*)&d[mf][nf][p]);
                    part[mf][p] = fmaf(wvs[col],   ftanh(f.x + qrow[col]),   part[mf][p]);
                    part[mf][p] = fmaf(wvs[col+1], ftanh(f.y + qrow[col+1]), part[mf][p]);
                }
            }
        #pragma unroll
        for (int mf = 0; mf < 2; mf++)
            #pragma unroll
            for (int p = 0; p < 2; p++){
                part[mf][p] += __shfl_xor_sync(0xffffffffu, part[mf][p], 1);
                part[mf][p] += __shfl_xor_sync(0xffffffffu, part[mf][p], 2);
            }
        if ((lane & 3) == 0){
            #pragma unroll
            for (int mf = 0; mf < 2; mf++)
                #pragma unroll
                for (int p = 0; p < 2; p++){
                    int row = warp_m*32 + mf*16 + (lane>>2) + p*8;
                    sred[warp_n*64 + row] = part[mf][p];
                }
        }
        __syncthreads();
        if (tid < TM){
            float e = __expf(sred[tid] + sred[64+tid] + sred[128+tid] + sred[192+tid] + bvv);
            g_escore[b*SEQ + s0 + tid] = e;
            sw[tid] = e;
            #pragma unroll
            for (int o = 16; o; o >>= 1) e += __shfl_xor_sync(0xffffffffu, e, o);
            if (lane == 0) wred[tid>>5] = e;
        }
        __syncthreads();

        /* fused context */
        {
            float acc[8] = {};
            #pragma unroll
            for (int r0 = 0; r0 < 8; r0++){
                int r = rq*8 + r0;
                uint32_t addr = ctx_base + (uint32_t)(r*128 + ((ctx_gr ^ (r&7))<<4));
                uint4 u;
                asm volatile("ld.shared.v4.b32 {%0,%1,%2,%3}, [%4];"
                    : "=r"(u.x),"=r"(u.y),"=r"(u.z),"=r"(u.w) : "r"(addr));
                float w = sw[r];
                float2 f0 = __half22float2(*(__half2*)&u.x);
                float2 f1 = __half22float2(*(__half2*)&u.y);
                float2 f2 = __half22float2(*(__half2*)&u.z);
                float2 f3 = __half22float2(*(__half2*)&u.w);
                acc[0] = fmaf(w, f0.x, acc[0]); acc[1] = fmaf(w, f0.y, acc[1]);
                acc[2] = fmaf(w, f1.x, acc[2]); acc[3] = fmaf(w, f1.y, acc[3]);
                acc[4] = fmaf(w, f2.x, acc[4]); acc[5] = fmaf(w, f2.y, acc[5]);
                acc[6] = fmaf(w, f3.x, acc[6]); acc[7] = fmaf(w, f3.y, acc[7]);
            }
            float* dst = sctx + rq*256 + cg8*8;
            *(float4*)dst = make_float4(acc[0],acc[1],acc[2],acc[3]);
            *(float4*)(dst+4) = make_float4(acc[4],acc[5],acc[6],acc[7]);
        }
        __syncthreads();
        if (tid < 128){
            float2* sc = (float2*)sctx;
            float2 a = sc[tid];
            #pragma unroll
            for (int q = 1; q < 8; q++){
                float2 t = sc[q*128 + tid];
                a.x += t.x; a.y += t.y;
            }
            ((float2*)g_pctx)[tile*128 + tid] = a;
        }
        if (tid == 0) g_psum[tile] = wred[0]+wred[1];
    }

    /* ---- grid barrier (monotonic; replay-safe) ---- */
    __syncthreads();
    if (tid == 0){
        __threadfence();
        unsigned my = atomicAdd(&g_arrive, 1u) + 1u;
        unsigned target = ((my + (GRID_A-1)) / GRID_A) * GRID_A;
        while (*((volatile unsigned*)&g_arrive) < target) __nanosleep(64);
        __threadfence();
    }
    __syncthreads();

    if (tid < BATCH){
        float s = 0.f;
        #pragma unroll 8
        for (int t = 0; t < 64; t++) s += g_psum[tid*64 + t];
        qrow[tid] = 1.f / s;
    }
    __syncthreads();

    for (int i = blockIdx.x*256 + tid; i < BATCH*SEQ; i += GRID_A*256)
        outw[i] = g_escore[i] * qrow[i >> 12];

    for (int i = blockIdx.x*256 + tid; i < BATCH*VDIM; i += GRID_A*256){
        int bb = i >> 8, dd2 = i & 255;
        float a = 0.f;
        #pragma unroll 8
        for (int t = 0; t < 64; t++) a += g_pctx[(bb*64 + t)*VDIM + dd2];
        outc[i] = a * qrow[bb];
    }
}

extern "C" void kernel_launch(void* const* d_in, const int* in_sizes, int n_in,
                              void* d_out, int out_size){
    (void)in_sizes; (void)n_in; (void)out_size;
    const float* query  = (const float*)d_in[0];
    const float* values = (const float*)d_in[1];
    const float* W1 = (const float*)d_in[2];
    const float* b1 = (const float*)d_in[3];
    const float* W2 = (const float*)d_in[4];
    const float* b2 = (const float*)d_in[5];
    const float* Wv = (const float*)d_in[6];
    const float* bv = (const float*)d_in[7];
    float* out = (float*)d_out;
    cudaFuncSetAttribute(k_scores, cudaFuncAttributeMaxDynamicSharedMemorySize, SM_TOTAL);
    k_prep<<<BATCH + 1, 128>>>(query, W1, b1, W2, b2);
    k_scores<<<GRID_A, 256, SM_TOTAL>>>(values, Wv, bv, out + BATCH*VDIM, out);
}